// round 1
// baseline (speedup 1.0000x reference)
#include <cuda_runtime.h>

#define ROWS 65536
#define H 256
#define IN_SHAPE 512
#define NA 32
#define NACT 16
#define G3 768   // 3*H

// ---------------- scratch (allocation-free: __device__ globals) -------------
__device__ float g_x [ROWS * H];
__device__ float g_gi[ROWS * G3];
__device__ float g_gh[ROWS * G3];
__device__ float g_h0[ROWS * H];
__device__ float g_h1[ROWS * H];
__device__ float g_c [ROWS * H];
__device__ float g_nb[ROWS * NA];
__device__ float g_invn[ROWS];

// ---------------- packed f32x2 helpers --------------------------------------
__device__ __forceinline__ unsigned long long pack2(float lo, float hi) {
    unsigned long long d;
    asm("mov.b64 %0, {%1, %2};" : "=l"(d) : "f"(lo), "f"(hi));
    return d;
}
__device__ __forceinline__ void unpack2(unsigned long long d, float& lo, float& hi) {
    asm("mov.b64 {%0, %1}, %2;" : "=f"(lo), "=f"(hi) : "l"(d));
}
__device__ __forceinline__ void fma2(unsigned long long& acc, unsigned long long a,
                                     unsigned long long b) {
    asm("fma.rn.f32x2 %0, %1, %2, %0;" : "+l"(acc) : "l"(a), "l"(b));
}

__device__ __forceinline__ float sigm(float x) { return 1.0f / (1.0f + __expf(-x)); }
__device__ __forceinline__ float tanh_fast(float x) {
    return 2.0f / (1.0f + __expf(-2.0f * x)) - 1.0f;
}

// ---------------- SGEMM (NT): C[m,n] = sum_k A[m,k]*B[n,k] + bias[n] --------
// BM=128, BN=128, BK=16, 256 threads, per-thread 8 rows x 8 cols via f32x2.
template <int RELU>
__global__ __launch_bounds__(256) void sgemm_nt(
    const float* __restrict__ A, const float* __restrict__ B,
    const float* __restrict__ bias, float* __restrict__ C,
    int M, int N, int K)
{
    __shared__ float As[16][132];
    __shared__ float Bs[16][132];

    const int tid = threadIdx.x;
    const int bm = blockIdx.y * 128;
    const int bn = blockIdx.x * 128;

    const int tr = tid >> 2;          // 0..63 (load row)
    const int tc = (tid & 3) << 2;    // 0,4,8,12 (load col base)
    const int ty = tid >> 4;          // 0..15 -> rows ty*8..ty*8+7
    const int tx = tid & 15;          // 0..15 -> cols tx*8..tx*8+7

    unsigned long long acc[4][8];
#pragma unroll
    for (int i = 0; i < 4; i++)
#pragma unroll
        for (int j = 0; j < 8; j++) acc[i][j] = 0ull;

    const float* Ap  = A + (long)(bm + tr) * K + tc;
    const float* Ap2 = Ap + (long)64 * K;
    const float* Bp  = B + (long)(bn + tr) * K + tc;
    const float* Bp2 = Bp + (long)64 * K;

    for (int k0 = 0; k0 < K; k0 += 16) {
        float4 a0 = *(const float4*)(Ap  + k0);
        float4 a1 = *(const float4*)(Ap2 + k0);
        float4 b0 = *(const float4*)(Bp  + k0);
        float4 b1 = *(const float4*)(Bp2 + k0);
        __syncthreads();
        As[tc + 0][tr]      = a0.x; As[tc + 1][tr]      = a0.y;
        As[tc + 2][tr]      = a0.z; As[tc + 3][tr]      = a0.w;
        As[tc + 0][tr + 64] = a1.x; As[tc + 1][tr + 64] = a1.y;
        As[tc + 2][tr + 64] = a1.z; As[tc + 3][tr + 64] = a1.w;
        Bs[tc + 0][tr]      = b0.x; Bs[tc + 1][tr]      = b0.y;
        Bs[tc + 2][tr]      = b0.z; Bs[tc + 3][tr]      = b0.w;
        Bs[tc + 0][tr + 64] = b1.x; Bs[tc + 1][tr + 64] = b1.y;
        Bs[tc + 2][tr + 64] = b1.z; Bs[tc + 3][tr + 64] = b1.w;
        __syncthreads();

#pragma unroll
        for (int kk = 0; kk < 16; kk++) {
            unsigned long long a2[4];
#pragma unroll
            for (int i = 0; i < 4; i++)
                a2[i] = *(const unsigned long long*)&As[kk][ty * 8 + 2 * i];
            float4 bv0 = *(const float4*)&Bs[kk][tx * 8];
            float4 bv1 = *(const float4*)&Bs[kk][tx * 8 + 4];
            unsigned long long b2[8];
            b2[0] = pack2(bv0.x, bv0.x); b2[1] = pack2(bv0.y, bv0.y);
            b2[2] = pack2(bv0.z, bv0.z); b2[3] = pack2(bv0.w, bv0.w);
            b2[4] = pack2(bv1.x, bv1.x); b2[5] = pack2(bv1.y, bv1.y);
            b2[6] = pack2(bv1.z, bv1.z); b2[7] = pack2(bv1.w, bv1.w);
#pragma unroll
            for (int i = 0; i < 4; i++)
#pragma unroll
                for (int j = 0; j < 8; j++) fma2(acc[i][j], a2[i], b2[j]);
        }
    }

    // epilogue
    float bb[8];
    *(float4*)&bb[0] = *(const float4*)&bias[bn + tx * 8];
    *(float4*)&bb[4] = *(const float4*)&bias[bn + tx * 8 + 4];

#pragma unroll
    for (int i = 0; i < 4; i++) {
        float lo[8], hi[8];
#pragma unroll
        for (int j = 0; j < 8; j++) unpack2(acc[i][j], lo[j], hi[j]);
        const int row0 = bm + ty * 8 + 2 * i;
        float v0[8], v1[8];
#pragma unroll
        for (int j = 0; j < 8; j++) {
            v0[j] = lo[j] + bb[j];
            v1[j] = hi[j] + bb[j];
            if (RELU) {
                v0[j] = fmaxf(v0[j], 0.0f);
                v1[j] = fmaxf(v1[j], 0.0f);
            }
        }
        float* c0 = C + (long)row0 * N + bn + tx * 8;
        float* c1 = c0 + N;
        *(float4*)c0       = make_float4(v0[0], v0[1], v0[2], v0[3]);
        *(float4*)(c0 + 4) = make_float4(v0[4], v0[5], v0[6], v0[7]);
        *(float4*)c1       = make_float4(v1[0], v1[1], v1[2], v1[3]);
        *(float4*)(c1 + 4) = make_float4(v1[4], v1[5], v1[6], v1[7]);
    }
}

// ---------------- GRU gate fusion -------------------------------------------
// h' = (1-z)*n + z*hstate ; r = sig(ir+hr), z = sig(iz+hz), n = tanh(in + r*hn)
__global__ __launch_bounds__(256) void gru_gates(
    const float* __restrict__ gi, const float* __restrict__ gh,
    const float* __restrict__ hstate,
    float* __restrict__ out0, float* __restrict__ out1)
{
    int idx = blockIdx.x * 256 + threadIdx.x;   // ROWS*64 total (float4 granularity)
    int row = idx >> 6;
    int c = (idx & 63) << 2;
    long gbase = (long)row * G3 + c;
    long hbase = (long)row * H + c;

    float4 ir = *(const float4*)&gi[gbase];
    float4 iz = *(const float4*)&gi[gbase + 256];
    float4 in_ = *(const float4*)&gi[gbase + 512];
    float4 hr = *(const float4*)&gh[gbase];
    float4 hz = *(const float4*)&gh[gbase + 256];
    float4 hn = *(const float4*)&gh[gbase + 512];
    float4 hv = *(const float4*)&hstate[hbase];

    float4 o;
    {
        float r = sigm(ir.x + hr.x), z = sigm(iz.x + hz.x);
        float n = tanh_fast(in_.x + r * hn.x);
        o.x = (1.0f - z) * n + z * hv.x;
    }
    {
        float r = sigm(ir.y + hr.y), z = sigm(iz.y + hz.y);
        float n = tanh_fast(in_.y + r * hn.y);
        o.y = (1.0f - z) * n + z * hv.y;
    }
    {
        float r = sigm(ir.z + hr.z), z = sigm(iz.z + hz.z);
        float n = tanh_fast(in_.z + r * hn.z);
        o.z = (1.0f - z) * n + z * hv.z;
    }
    {
        float r = sigm(ir.w + hr.w), z = sigm(iz.w + hz.w);
        float n = tanh_fast(in_.w + r * hn.w);
        o.w = (1.0f - z) * n + z * hv.w;
    }
    *(float4*)&out0[hbase] = o;
    if (out1) *(float4*)&out1[hbase] = o;
}

// ---------------- neighbor extraction ----------------------------------------
// nb[row][j]: off-diagonal adjacency weights from obs cols 260 + 8*k;
// invn[row] = 1 / sum_j nb[row][j]
__global__ __launch_bounds__(256) void nb_kernel(
    const float* __restrict__ inp, float* __restrict__ nb, float* __restrict__ invn)
{
    int idx = blockIdx.x * 256 + threadIdx.x;   // ROWS*32 total
    int row = idx >> 5;
    int j = idx & 31;
    int i = row & 31;
    float v = 0.0f;
    if (j != i) {
        int k = (j > i) ? (j - 1) : j;
        v = inp[(long)row * IN_SHAPE + 260 + 8 * k];
    }
    float s = v;
#pragma unroll
    for (int o = 16; o > 0; o >>= 1) s += __shfl_xor_sync(0xffffffffu, s, o);
    nb[idx] = v;
    if (j == 0) invn[row] = 1.0f / s;
}

// ---------------- comm mix: c[b,i,:] = (sum_j A[i,j] h[b,j,:]) * invn --------
__global__ __launch_bounds__(256) void comm_mix(
    const float* __restrict__ h, const float* __restrict__ nb,
    const float* __restrict__ invn, float* __restrict__ out)
{
    __shared__ float hs[32][256];
    __shared__ float At[32][36];   // At[j][i]
    __shared__ float sinv[32];

    int b = blockIdx.x;
    int tid = threadIdx.x;
    const float* hb = h + (long)b * 32 * 256;

#pragma unroll
    for (int t = tid; t < 2048; t += 256) {
        int r = t >> 6;
        int c4 = (t & 63) << 2;
        *(float4*)&hs[r][c4] = *(const float4*)&hb[r * 256 + c4];
    }
#pragma unroll
    for (int t = tid; t < 1024; t += 256) {
        int i = t >> 5;
        int j = t & 31;
        At[j][i] = nb[(long)(b * 32 + i) * 32 + j];
    }
    if (tid < 32) sinv[tid] = invn[b * 32 + tid];
    __syncthreads();

    float acc[32];
#pragma unroll
    for (int i = 0; i < 32; i++) acc[i] = 0.0f;

#pragma unroll 4
    for (int j = 0; j < 32; j++) {
        float hv = hs[j][tid];
#pragma unroll
        for (int i4 = 0; i4 < 32; i4 += 4) {
            float4 a = *(const float4*)&At[j][i4];
            acc[i4 + 0] += a.x * hv;
            acc[i4 + 1] += a.y * hv;
            acc[i4 + 2] += a.z * hv;
            acc[i4 + 3] += a.w * hv;
        }
    }
#pragma unroll
    for (int i = 0; i < 32; i++)
        out[(long)(b * 32 + i) * 256 + tid] = acc[i] * sinv[i];
}

// ---------------- q projection: q = h @ W2^T + b2 ----------------------------
__global__ __launch_bounds__(256) void qproj(
    const float* __restrict__ h, const float* __restrict__ W2,
    const float* __restrict__ b2, float* __restrict__ q)
{
    __shared__ float ws[16][260];
    __shared__ float hsm[16][256];
    int tid = threadIdx.x;

#pragma unroll
    for (int t = tid; t < 1024; t += 256) {
        int n = t >> 6;
        int k4 = (t & 63) << 2;
        *(float4*)&ws[n][k4] = *(const float4*)&W2[n * 256 + k4];
    }
    const float* hb = h + (long)blockIdx.x * 16 * 256;
#pragma unroll
    for (int t = tid; t < 1024; t += 256) {
        int r = t >> 6;
        int k4 = (t & 63) << 2;
        *(float4*)&hsm[r][k4] = *(const float4*)&hb[r * 256 + k4];
    }
    __syncthreads();

    int r = tid >> 4;
    int n = tid & 15;
    float s = 0.0f;
#pragma unroll 8
    for (int k = 0; k < 256; k += 4) {
        float4 hv = *(const float4*)&hsm[r][k];
        float4 wv = *(const float4*)&ws[n][k];
        s += hv.x * wv.x + hv.y * wv.y + hv.z * wv.z + hv.w * wv.w;
    }
    q[(long)(blockIdx.x * 16 + r) * 16 + n] = s + b2[n];
}

// ---------------- orchestration ----------------------------------------------
extern "C" void kernel_launch(void* const* d_in, const int* in_sizes, int n_in,
                              void* d_out, int out_size)
{
    (void)in_sizes; (void)n_in; (void)out_size;
    const float* inputs = (const float*)d_in[0];
    const float* hidden = (const float*)d_in[1];
    const float* W1     = (const float*)d_in[2];
    const float* b1     = (const float*)d_in[3];
    const float* rWih   = (const float*)d_in[4];
    const float* rWhh   = (const float*)d_in[5];
    const float* rbih   = (const float*)d_in[6];
    const float* rbhh   = (const float*)d_in[7];
    const float* cWih   = (const float*)d_in[8];
    const float* cWhh   = (const float*)d_in[9];
    const float* cbih   = (const float*)d_in[10];
    const float* cbhh   = (const float*)d_in[11];
    const float* W2     = (const float*)d_in[12];
    const float* b2     = (const float*)d_in[13];

    float* q_out = (float*)d_out;
    float* hrnn_out = q_out + (long)ROWS * NACT;

    float *x, *gi, *gh, *h0, *h1, *c, *nb, *invn;
    cudaGetSymbolAddress((void**)&x, g_x);
    cudaGetSymbolAddress((void**)&gi, g_gi);
    cudaGetSymbolAddress((void**)&gh, g_gh);
    cudaGetSymbolAddress((void**)&h0, g_h0);
    cudaGetSymbolAddress((void**)&h1, g_h1);
    cudaGetSymbolAddress((void**)&c, g_c);
    cudaGetSymbolAddress((void**)&nb, g_nb);
    cudaGetSymbolAddress((void**)&invn, g_invn);

    dim3 blk(256);

    // x = relu(inputs @ W1^T + b1)
    sgemm_nt<1><<<dim3(H / 128, ROWS / 128), blk>>>(inputs, W1, b1, x, ROWS, H, IN_SHAPE);

    // h_rnn = GRU(x, hidden)
    sgemm_nt<0><<<dim3(G3 / 128, ROWS / 128), blk>>>(x, rWih, rbih, gi, ROWS, G3, H);
    sgemm_nt<0><<<dim3(G3 / 128, ROWS / 128), blk>>>(hidden, rWhh, rbhh, gh, ROWS, G3, H);
    gru_gates<<<ROWS * 64 / 256, blk>>>(gi, gh, hidden, h0, hrnn_out);

    // neighbor weights + 1/sum
    nb_kernel<<<ROWS * 32 / 256, blk>>>(inputs, nb, invn);

    float* hc = h0;
    float* hn = h1;
    for (int s = 0; s < 4; s++) {
        comm_mix<<<ROWS / NA, blk>>>(hc, nb, invn, c);
        // h = GRU(x=h, h=c): gi from h, gh from c, state = c
        sgemm_nt<0><<<dim3(G3 / 128, ROWS / 128), blk>>>(hc, cWih, cbih, gi, ROWS, G3, H);
        sgemm_nt<0><<<dim3(G3 / 128, ROWS / 128), blk>>>(c, cWhh, cbhh, gh, ROWS, G3, H);
        gru_gates<<<ROWS * 64 / 256, blk>>>(gi, gh, c, hn, nullptr);
        float* t = hc; hc = hn; hn = t;
    }

    // q = h @ W2^T + b2
    qproj<<<ROWS / 16, blk>>>(hc, W2, b2, q_out);
}

// round 3
// speedup vs baseline: 2.5586x; 2.5586x over previous
#include <cuda_runtime.h>
#include <cstdint>

#define ROWS 65536
#define H 256
#define IN_SHAPE 512
#define NA 32
#define NACT 16
#define G3 768   // 3*H

// ---------------- scratch (allocation-free: __device__ globals) -------------
__device__ float g_x [(size_t)ROWS * H];
__device__ float g_gi[(size_t)ROWS * G3];
__device__ float g_gh[(size_t)ROWS * G3];
__device__ float g_h0[(size_t)ROWS * H];
__device__ float g_h1[(size_t)ROWS * H];
__device__ float g_c [(size_t)ROWS * H];
__device__ float g_nb[(size_t)ROWS * NA];
__device__ float g_invn[(size_t)ROWS];

__device__ __forceinline__ uint32_t f2tf32(float v) {
    uint32_t u;
    asm("cvt.rna.tf32.f32 %0, %1;" : "=r"(u) : "f"(v));
    return u;
}

// ---------------- tf32 mma.sync GEMM ----------------------------------------
// C[m,n] = sum_k A[m,k]*B[n,k] + bias[n]   (A: MxK, B: NxK, row-major fp32)
// BM=128, BN=128, BK=32; 8 warps as 2(M) x 4(N); warp tile 64x32.
template <int RELU>
__global__ __launch_bounds__(256) void gemm_mma(
    const float* __restrict__ A, const float* __restrict__ B,
    const float* __restrict__ bias, float* __restrict__ C,
    int M, int N, int K)
{
    __shared__ uint32_t As[128][36];
    __shared__ uint32_t Bs[128][36];

    const int tid = threadIdx.x;
    const int wid = tid >> 5;
    const int lane = tid & 31;
    const int gr = lane >> 2;   // group id (0..7)
    const int tg = lane & 3;    // thread-in-group

    const int bm = blockIdx.y * 128;
    const int bn = blockIdx.x * 128;
    const int wm = (wid & 1) * 64;   // warp M offset
    const int wn = (wid >> 1) * 32;  // warp N offset

    // global load mapping: each thread loads 4 float4 from A and 4 from B
    const int lr = tid >> 3;        // 0..31 (row), rows lr, lr+32, lr+64, lr+96
    const int lf = tid & 7;         // float4 index within 32-k chunk

    const float* Ap = A + (long)(bm + lr) * K + lf * 4;
    const float* Bp = B + (long)(bn + lr) * K + lf * 4;
    const long strideA = (long)32 * K;

    float acc[4][4][4];
#pragma unroll
    for (int i = 0; i < 4; i++)
#pragma unroll
        for (int j = 0; j < 4; j++)
#pragma unroll
            for (int e = 0; e < 4; e++) acc[i][j][e] = 0.0f;

    float4 ar[4], br[4];
#pragma unroll
    for (int i = 0; i < 4; i++) {
        ar[i] = *(const float4*)(Ap + i * strideA);
        br[i] = *(const float4*)(Bp + i * strideA);
    }

    for (int k0 = 0; k0 < K; k0 += 32) {
        __syncthreads();
#pragma unroll
        for (int i = 0; i < 4; i++) {
            const int r = lr + i * 32;
            As[r][lf * 4 + 0] = f2tf32(ar[i].x);
            As[r][lf * 4 + 1] = f2tf32(ar[i].y);
            As[r][lf * 4 + 2] = f2tf32(ar[i].z);
            As[r][lf * 4 + 3] = f2tf32(ar[i].w);
            Bs[r][lf * 4 + 0] = f2tf32(br[i].x);
            Bs[r][lf * 4 + 1] = f2tf32(br[i].y);
            Bs[r][lf * 4 + 2] = f2tf32(br[i].z);
            Bs[r][lf * 4 + 3] = f2tf32(br[i].w);
        }
        __syncthreads();

        if (k0 + 32 < K) {
#pragma unroll
            for (int i = 0; i < 4; i++) {
                ar[i] = *(const float4*)(Ap + (k0 + 32) + i * strideA);
                br[i] = *(const float4*)(Bp + (k0 + 32) + i * strideA);
            }
        }

#pragma unroll
        for (int kk = 0; kk < 4; kk++) {
            const int kb = kk * 8;
            uint32_t af[4][4];
            uint32_t bf[4][2];
#pragma unroll
            for (int i = 0; i < 4; i++) {
                const int r0 = wm + 16 * i + gr;
                af[i][0] = As[r0][kb + tg];
                af[i][1] = As[r0 + 8][kb + tg];
                af[i][2] = As[r0][kb + tg + 4];
                af[i][3] = As[r0 + 8][kb + tg + 4];
            }
#pragma unroll
            for (int j = 0; j < 4; j++) {
                const int n0 = wn + 8 * j + gr;
                bf[j][0] = Bs[n0][kb + tg];
                bf[j][1] = Bs[n0][kb + tg + 4];
            }
#pragma unroll
            for (int i = 0; i < 4; i++)
#pragma unroll
                for (int j = 0; j < 4; j++) {
                    asm volatile(
                        "mma.sync.aligned.m16n8k8.row.col.f32.tf32.tf32.f32 "
                        "{%0,%1,%2,%3}, {%4,%5,%6,%7}, {%8,%9}, {%0,%1,%2,%3};"
                        : "+f"(acc[i][j][0]), "+f"(acc[i][j][1]),
                          "+f"(acc[i][j][2]), "+f"(acc[i][j][3])
                        : "r"(af[i][0]), "r"(af[i][1]), "r"(af[i][2]), "r"(af[i][3]),
                          "r"(bf[j][0]), "r"(bf[j][1]));
                }
        }
    }

    // epilogue: c0/c1 at (row, col..col+1), c2/c3 at (row+8, col..col+1)
#pragma unroll
    for (int j = 0; j < 4; j++) {
        const int col = bn + wn + 8 * j + 2 * tg;
        const float2 bb = *(const float2*)&bias[col];
#pragma unroll
        for (int i = 0; i < 4; i++) {
            const long r0 = (long)(bm + wm + 16 * i + gr);
            float2 v0, v1;
            v0.x = acc[i][j][0] + bb.x;
            v0.y = acc[i][j][1] + bb.y;
            v1.x = acc[i][j][2] + bb.x;
            v1.y = acc[i][j][3] + bb.y;
            if (RELU) {
                v0.x = fmaxf(v0.x, 0.0f); v0.y = fmaxf(v0.y, 0.0f);
                v1.x = fmaxf(v1.x, 0.0f); v1.y = fmaxf(v1.y, 0.0f);
            }
            *(float2*)&C[r0 * N + col] = v0;
            *(float2*)&C[(r0 + 8) * N + col] = v1;
        }
    }
}

// ---------------- GRU gate fusion -------------------------------------------
__device__ __forceinline__ float sigm(float x) { return 1.0f / (1.0f + __expf(-x)); }
__device__ __forceinline__ float tanh_fast(float x) {
    return 2.0f / (1.0f + __expf(-2.0f * x)) - 1.0f;
}

__global__ __launch_bounds__(256) void gru_gates(
    const float* __restrict__ gi, const float* __restrict__ gh,
    const float* __restrict__ hstate,
    float* __restrict__ out0, float* __restrict__ out1)
{
    int idx = blockIdx.x * 256 + threadIdx.x;
    int row = idx >> 6;
    int c = (idx & 63) << 2;
    long gbase = (long)row * G3 + c;
    long hbase = (long)row * H + c;

    float4 ir = *(const float4*)&gi[gbase];
    float4 iz = *(const float4*)&gi[gbase + 256];
    float4 in_ = *(const float4*)&gi[gbase + 512];
    float4 hr = *(const float4*)&gh[gbase];
    float4 hz = *(const float4*)&gh[gbase + 256];
    float4 hn = *(const float4*)&gh[gbase + 512];
    float4 hv = *(const float4*)&hstate[hbase];

    float4 o;
    { float r = sigm(ir.x + hr.x), z = sigm(iz.x + hz.x);
      float n = tanh_fast(in_.x + r * hn.x); o.x = (1.0f - z) * n + z * hv.x; }
    { float r = sigm(ir.y + hr.y), z = sigm(iz.y + hz.y);
      float n = tanh_fast(in_.y + r * hn.y); o.y = (1.0f - z) * n + z * hv.y; }
    { float r = sigm(ir.z + hr.z), z = sigm(iz.z + hz.z);
      float n = tanh_fast(in_.z + r * hn.z); o.z = (1.0f - z) * n + z * hv.z; }
    { float r = sigm(ir.w + hr.w), z = sigm(iz.w + hz.w);
      float n = tanh_fast(in_.w + r * hn.w); o.w = (1.0f - z) * n + z * hv.w; }
    *(float4*)&out0[hbase] = o;
    if (out1) *(float4*)&out1[hbase] = o;
}

// ---------------- neighbor extraction ----------------------------------------
__global__ __launch_bounds__(256) void nb_kernel(
    const float* __restrict__ inp, float* __restrict__ nb, float* __restrict__ invn)
{
    int idx = blockIdx.x * 256 + threadIdx.x;
    int row = idx >> 5;
    int j = idx & 31;
    int i = row & 31;
    float v = 0.0f;
    if (j != i) {
        int k = (j > i) ? (j - 1) : j;
        v = inp[(long)row * IN_SHAPE + 260 + 8 * k];
    }
    float s = v;
#pragma unroll
    for (int o = 16; o > 0; o >>= 1) s += __shfl_xor_sync(0xffffffffu, s, o);
    nb[idx] = v;
    if (j == 0) invn[row] = 1.0f / s;
}

// ---------------- comm mix ---------------------------------------------------
__global__ __launch_bounds__(256) void comm_mix(
    const float* __restrict__ h, const float* __restrict__ nb,
    const float* __restrict__ invn, float* __restrict__ out)
{
    __shared__ float hs[32][256];
    __shared__ float At[32][36];
    __shared__ float sinv[32];

    int b = blockIdx.x;
    int tid = threadIdx.x;
    const float* hb = h + (long)b * 32 * 256;

#pragma unroll
    for (int t = tid; t < 2048; t += 256) {
        int r = t >> 6;
        int c4 = (t & 63) << 2;
        *(float4*)&hs[r][c4] = *(const float4*)&hb[r * 256 + c4];
    }
#pragma unroll
    for (int t = tid; t < 1024; t += 256) {
        int i = t >> 5;
        int j = t & 31;
        At[j][i] = nb[(long)(b * 32 + i) * 32 + j];
    }
    if (tid < 32) sinv[tid] = invn[b * 32 + tid];
    __syncthreads();

    float acc[32];
#pragma unroll
    for (int i = 0; i < 32; i++) acc[i] = 0.0f;

#pragma unroll 4
    for (int j = 0; j < 32; j++) {
        float hv = hs[j][tid];
#pragma unroll
        for (int i4 = 0; i4 < 32; i4 += 4) {
            float4 a = *(const float4*)&At[j][i4];
            acc[i4 + 0] += a.x * hv;
            acc[i4 + 1] += a.y * hv;
            acc[i4 + 2] += a.z * hv;
            acc[i4 + 3] += a.w * hv;
        }
    }
#pragma unroll
    for (int i = 0; i < 32; i++)
        out[(long)(b * 32 + i) * 256 + tid] = acc[i] * sinv[i];
}

// ---------------- q projection -----------------------------------------------
__global__ __launch_bounds__(256) void qproj(
    const float* __restrict__ h, const float* __restrict__ W2,
    const float* __restrict__ b2, float* __restrict__ q)
{
    __shared__ float ws[16][260];
    __shared__ float hsm[16][256];
    int tid = threadIdx.x;

#pragma unroll
    for (int t = tid; t < 1024; t += 256) {
        int n = t >> 6;
        int k4 = (t & 63) << 2;
        *(float4*)&ws[n][k4] = *(const float4*)&W2[n * 256 + k4];
    }
    const float* hb = h + (long)blockIdx.x * 16 * 256;
#pragma unroll
    for (int t = tid; t < 1024; t += 256) {
        int r = t >> 6;
        int k4 = (t & 63) << 2;
        *(float4*)&hsm[r][k4] = *(const float4*)&hb[r * 256 + k4];
    }
    __syncthreads();

    int r = tid >> 4;
    int n = tid & 15;
    float s = 0.0f;
#pragma unroll 8
    for (int k = 0; k < 256; k += 4) {
        float4 hv = *(const float4*)&hsm[r][k];
        float4 wv = *(const float4*)&ws[n][k];
        s += hv.x * wv.x + hv.y * wv.y + hv.z * wv.z + hv.w * wv.w;
    }
    q[(long)(blockIdx.x * 16 + r) * 16 + n] = s + b2[n];
}

// ---------------- orchestration ----------------------------------------------
extern "C" void kernel_launch(void* const* d_in, const int* in_sizes, int n_in,
                              void* d_out, int out_size)
{
    (void)in_sizes; (void)n_in; (void)out_size;
    const float* inputs = (const float*)d_in[0];
    const float* hidden = (const float*)d_in[1];
    const float* W1     = (const float*)d_in[2];
    const float* b1     = (const float*)d_in[3];
    const float* rWih   = (const float*)d_in[4];
    const float* rWhh   = (const float*)d_in[5];
    const float* rbih   = (const float*)d_in[6];
    const float* rbhh   = (const float*)d_in[7];
    const float* cWih   = (const float*)d_in[8];
    const float* cWhh   = (const float*)d_in[9];
    const float* cbih   = (const float*)d_in[10];
    const float* cbhh   = (const float*)d_in[11];
    const float* W2     = (const float*)d_in[12];
    const float* b2     = (const float*)d_in[13];

    float* q_out = (float*)d_out;
    float* hrnn_out = q_out + (long)ROWS * NACT;

    float *x, *gi, *gh, *h0, *h1, *c, *nb, *invn;
    cudaGetSymbolAddress((void**)&x, g_x);
    cudaGetSymbolAddress((void**)&gi, g_gi);
    cudaGetSymbolAddress((void**)&gh, g_gh);
    cudaGetSymbolAddress((void**)&h0, g_h0);
    cudaGetSymbolAddress((void**)&h1, g_h1);
    cudaGetSymbolAddress((void**)&c, g_c);
    cudaGetSymbolAddress((void**)&nb, g_nb);
    cudaGetSymbolAddress((void**)&invn, g_invn);

    dim3 blk(256);

    // x = relu(inputs @ W1^T + b1)
    gemm_mma<1><<<dim3(H / 128, ROWS / 128), blk>>>(inputs, W1, b1, x, ROWS, H, IN_SHAPE);

    // h_rnn = GRU(x, hidden)
    gemm_mma<0><<<dim3(G3 / 128, ROWS / 128), blk>>>(x, rWih, rbih, gi, ROWS, G3, H);
    gemm_mma<0><<<dim3(G3 / 128, ROWS / 128), blk>>>(hidden, rWhh, rbhh, gh, ROWS, G3, H);
    gru_gates<<<ROWS * 64 / 256, blk>>>(gi, gh, hidden, h0, hrnn_out);

    nb_kernel<<<ROWS * 32 / 256, blk>>>(inputs, nb, invn);

    float* hc = h0;
    float* hn = h1;
    for (int s = 0; s < 4; s++) {
        comm_mix<<<ROWS / NA, blk>>>(hc, nb, invn, c);
        gemm_mma<0><<<dim3(G3 / 128, ROWS / 128), blk>>>(hc, cWih, cbih, gi, ROWS, G3, H);
        gemm_mma<0><<<dim3(G3 / 128, ROWS / 128), blk>>>(c, cWhh, cbhh, gh, ROWS, G3, H);
        gru_gates<<<ROWS * 64 / 256, blk>>>(gi, gh, c, hn, nullptr);
        float* t2 = hc; hc = hn; hn = t2;
    }

    qproj<<<ROWS / 16, blk>>>(hc, W2, b2, q_out);
}